// round 3
// baseline (speedup 1.0000x reference)
#include <cuda_runtime.h>
#include <math_constants.h>

#define N_IN   16384
#define NCONV  128
#define KMAX   11
#define TPB    256
#define CPB    16   // convs per block

__device__ __forceinline__ float warpReduceMax(float v) {
#pragma unroll
    for (int o = 16; o > 0; o >>= 1)
        v = fmaxf(v, __shfl_xor_sync(0xffffffffu, v, o));
    return v;
}
__device__ __forceinline__ int warpReduceSum(int v) {
#pragma unroll
    for (int o = 16; o > 0; o >>= 1)
        v += __shfl_xor_sync(0xffffffffu, v, o);
    return v;
}

// Read element c of an integer metadata array that may be int64 or int32.
__device__ __forceinline__ int meta_at(const void* arr, int c, bool is64) {
    if (is64) return (int)((const long long*)arr)[c];
    return ((const int*)arr)[c];
}

// Compute per-thread partial (max, neg-count) for one conv.
// xs: smem copy of x row, with xs[N_IN] == 0.0f sentinel for padding.
template <int K>
__device__ __forceinline__ void conv_feat(
    const float* __restrict__ xs,
    const float* __restrict__ wrow, float bias,
    int d, int p, int L,
    float& mx_out, int& neg_out)
{
    float w[K];
#pragma unroll
    for (int j = 0; j < K; j++) w[j] = wrow[j];
    int off[K];
#pragma unroll
    for (int j = 0; j < K; j++) off[j] = j * d;

    float mx = -CUDART_INF_F;
    int   neg = 0;
    const int tid = threadIdx.x;

    // middle zone [m_lo, m_hi): all K taps in-range (t>=p and t-p+(K-1)d <= N-1)
    const int m_lo = min(p, L);
    const int m_hi = max(m_lo, L - p);

    // ---- left edge: clamped taps ----
    for (int t = tid; t < m_lo; t += TPB) {
        float y = bias;
#pragma unroll
        for (int j = 0; j < K; j++) {
            int idx = t - p + off[j];
            unsigned ui = min((unsigned)idx, (unsigned)N_IN); // OOB -> sentinel
            y = fmaf(w[j], xs[ui], y);
        }
        mx = fmaxf(mx, y);
        neg += (int)(__float_as_uint(y) >> 31);
    }

    // ---- middle: no bounds checks (hot loop) ----
    for (int t = m_lo + tid; t < m_hi; t += TPB) {
        const float* xb = xs + (t - p);
        float y = bias;
#pragma unroll
        for (int j = 0; j < K; j++)
            y = fmaf(w[j], xb[off[j]], y);
        mx = fmaxf(mx, y);
        neg += (int)(__float_as_uint(y) >> 31);
    }

    // ---- right edge: clamped taps ----
    for (int t = m_hi + tid; t < L; t += TPB) {
        float y = bias;
#pragma unroll
        for (int j = 0; j < K; j++) {
            int idx = t - p + off[j];
            unsigned ui = min((unsigned)idx, (unsigned)N_IN);
            y = fmaf(w[j], xs[ui], y);
        }
        mx = fmaxf(mx, y);
        neg += (int)(__float_as_uint(y) >> 31);
    }

    mx_out = mx;
    neg_out = neg;
}

__global__ void __launch_bounds__(TPB)
feat_kernel(const float* __restrict__ x,
            const float* __restrict__ W,
            const float* __restrict__ B,
            const void* __restrict__ KS,
            const void* __restrict__ DS,
            const void* __restrict__ PS,
            float* __restrict__ out)
{
    extern __shared__ float xs[];   // N_IN + sentinel
    const int b = blockIdx.y;

    // Load x row into smem (float4 vectorized).
    {
        const float4* xr4 = (const float4*)(x + (size_t)b * N_IN);
        float4* xs4 = (float4*)xs;
        for (int i = threadIdx.x; i < N_IN / 4; i += TPB)
            xs4[i] = xr4[i];
        if (threadIdx.x == 0) xs[N_IN] = 0.0f;
    }

    __shared__ float rmax[TPB / 32];
    __shared__ int   rneg[TPB / 32];
    __syncthreads();

    // Detect int64 vs int32 metadata: kernel_sizes[0] in [7,11], so for int64
    // the second 32-bit word is 0; for int32 it is kernel_sizes[1] (>=7).
    const bool is64 = (((const int*)KS)[1] == 0);

    const int c0 = blockIdx.x * CPB;
    for (int c = c0; c < c0 + CPB; ++c) {
        const int k = meta_at(KS, c, is64);
        const int d = meta_at(DS, c, is64);
        const int p = meta_at(PS, c, is64);
        const int L = N_IN + 2 * p - d * (k - 1);

        const float* wrow = W + c * KMAX;
        const float bias  = B[c];

        float mx; int neg;
        if (k == 7)       conv_feat<7 >(xs, wrow, bias, d, p, L, mx, neg);
        else if (k == 9)  conv_feat<9 >(xs, wrow, bias, d, p, L, mx, neg);
        else              conv_feat<11>(xs, wrow, bias, d, p, L, mx, neg);

        // block reduction
        mx  = warpReduceMax(mx);
        neg = warpReduceSum(neg);
        const int warp = threadIdx.x >> 5;
        const int lane = threadIdx.x & 31;
        if (lane == 0) { rmax[warp] = mx; rneg[warp] = neg; }
        __syncthreads();
        if (threadIdx.x == 0) {
            float m = rmax[0]; int n = rneg[0];
#pragma unroll
            for (int i = 1; i < TPB / 32; i++) {
                m = fmaxf(m, rmax[i]);
                n += rneg[i];
            }
            const size_t base = (size_t)b * (2 * NCONV) + 2 * c;
            out[base]     = m;
            out[base + 1] = (float)(L - n) / (float)L;   // ppv = count(y>=0)/L
        }
        __syncthreads();   // protect rmax/rneg reuse for next conv
    }
}

extern "C" void kernel_launch(void* const* d_in, const int* in_sizes, int n_in,
                              void* d_out, int out_size)
{
    const float* x  = (const float*)d_in[0];
    const float* W  = (const float*)d_in[1];
    const float* B  = (const float*)d_in[2];
    const void*  KS = d_in[3];
    const void*  DS = d_in[4];
    const void*  PS = d_in[5];
    float* out = (float*)d_out;

    const int batch = in_sizes[0] / N_IN;   // 256

    const size_t smem = (N_IN + 16) * sizeof(float);  // row + sentinel + pad
    cudaFuncSetAttribute(feat_kernel,
                         cudaFuncAttributeMaxDynamicSharedMemorySize,
                         (int)smem);

    dim3 grid(NCONV / CPB, batch);
    feat_kernel<<<grid, TPB, smem>>>(x, W, B, KS, DS, PS, out);
}

// round 4
// speedup vs baseline: 1.0017x; 1.0017x over previous
#include <cuda_runtime.h>
#include <math_constants.h>

#define N_IN   16384
#define NCONV  128
#define KMAX   11
#define TPB    256
#define CPB    16   // convs per block

__device__ __forceinline__ float warpReduceMax(float v) {
#pragma unroll
    for (int o = 16; o > 0; o >>= 1)
        v = fmaxf(v, __shfl_xor_sync(0xffffffffu, v, o));
    return v;
}
__device__ __forceinline__ int warpReduceSum(int v) {
#pragma unroll
    for (int o = 16; o > 0; o >>= 1)
        v += __shfl_xor_sync(0xffffffffu, v, o);
    return v;
}

// Read element c of an integer metadata array that may be int64 or int32.
__device__ __forceinline__ int meta_at(const void* arr, int c, bool is64) {
    if (is64) return (int)((const long long*)arr)[c];
    return ((const int*)arr)[c];
}

// Compute per-thread partial (max, neg-count) for one conv.
// xs: smem copy of x row, with xs[N_IN] == 0.0f sentinel for padding.
template <int K>
__device__ __forceinline__ void conv_feat(
    const float* __restrict__ xs,
    const float* __restrict__ wrow, float bias,
    int d, int p, int L,
    float& mx_out, int& neg_out)
{
    float w[K];
#pragma unroll
    for (int j = 0; j < K; j++) w[j] = wrow[j];
    int off[K];
#pragma unroll
    for (int j = 0; j < K; j++) off[j] = j * d;

    float mx = -CUDART_INF_F;
    int   neg = 0;
    const int tid = threadIdx.x;

    // middle zone [m_lo, m_hi): all K taps in-range (t>=p and t-p+(K-1)d <= N-1)
    const int m_lo = min(p, L);
    const int m_hi = max(m_lo, L - p);

    // ---- left edge: clamped taps ----
    for (int t = tid; t < m_lo; t += TPB) {
        float y = bias;
#pragma unroll
        for (int j = 0; j < K; j++) {
            int idx = t - p + off[j];
            unsigned ui = min((unsigned)idx, (unsigned)N_IN); // OOB -> sentinel
            y = fmaf(w[j], xs[ui], y);
        }
        mx = fmaxf(mx, y);
        neg += (int)(__float_as_uint(y) >> 31);
    }

    // ---- middle: no bounds checks (hot loop) ----
    for (int t = m_lo + tid; t < m_hi; t += TPB) {
        const float* xb = xs + (t - p);
        float y = bias;
#pragma unroll
        for (int j = 0; j < K; j++)
            y = fmaf(w[j], xb[off[j]], y);
        mx = fmaxf(mx, y);
        neg += (int)(__float_as_uint(y) >> 31);
    }

    // ---- right edge: clamped taps ----
    for (int t = m_hi + tid; t < L; t += TPB) {
        float y = bias;
#pragma unroll
        for (int j = 0; j < K; j++) {
            int idx = t - p + off[j];
            unsigned ui = min((unsigned)idx, (unsigned)N_IN);
            y = fmaf(w[j], xs[ui], y);
        }
        mx = fmaxf(mx, y);
        neg += (int)(__float_as_uint(y) >> 31);
    }

    mx_out = mx;
    neg_out = neg;
}

__global__ void __launch_bounds__(TPB)
feat_kernel(const float* __restrict__ x,
            const float* __restrict__ W,
            const float* __restrict__ B,
            const void* __restrict__ KS,
            const void* __restrict__ DS,
            const void* __restrict__ PS,
            float* __restrict__ out)
{
    extern __shared__ float xs[];   // N_IN + sentinel
    const int b = blockIdx.y;

    // Load x row into smem (float4 vectorized).
    {
        const float4* xr4 = (const float4*)(x + (size_t)b * N_IN);
        float4* xs4 = (float4*)xs;
        for (int i = threadIdx.x; i < N_IN / 4; i += TPB)
            xs4[i] = xr4[i];
        if (threadIdx.x == 0) xs[N_IN] = 0.0f;
    }

    __shared__ float rmax[TPB / 32];
    __shared__ int   rneg[TPB / 32];
    __syncthreads();

    // Detect int64 vs int32 metadata: kernel_sizes[0] in [7,11], so for int64
    // the second 32-bit word is 0; for int32 it is kernel_sizes[1] (>=7).
    const bool is64 = (((const int*)KS)[1] == 0);

    const int c0 = blockIdx.x * CPB;
    for (int c = c0; c < c0 + CPB; ++c) {
        const int k = meta_at(KS, c, is64);
        const int d = meta_at(DS, c, is64);
        const int p = meta_at(PS, c, is64);
        const int L = N_IN + 2 * p - d * (k - 1);

        const float* wrow = W + c * KMAX;
        const float bias  = B[c];

        float mx; int neg;
        if (k == 7)       conv_feat<7 >(xs, wrow, bias, d, p, L, mx, neg);
        else if (k == 9)  conv_feat<9 >(xs, wrow, bias, d, p, L, mx, neg);
        else              conv_feat<11>(xs, wrow, bias, d, p, L, mx, neg);

        // block reduction
        mx  = warpReduceMax(mx);
        neg = warpReduceSum(neg);
        const int warp = threadIdx.x >> 5;
        const int lane = threadIdx.x & 31;
        if (lane == 0) { rmax[warp] = mx; rneg[warp] = neg; }
        __syncthreads();
        if (threadIdx.x == 0) {
            float m = rmax[0]; int n = rneg[0];
#pragma unroll
            for (int i = 1; i < TPB / 32; i++) {
                m = fmaxf(m, rmax[i]);
                n += rneg[i];
            }
            const size_t base = (size_t)b * (2 * NCONV) + 2 * c;
            out[base]     = m;
            out[base + 1] = (float)(L - n) / (float)L;   // ppv = count(y>=0)/L
        }
        __syncthreads();   // protect rmax/rneg reuse for next conv
    }
}

extern "C" void kernel_launch(void* const* d_in, const int* in_sizes, int n_in,
                              void* d_out, int out_size)
{
    const float* x  = (const float*)d_in[0];
    const float* W  = (const float*)d_in[1];
    const float* B  = (const float*)d_in[2];
    const void*  KS = d_in[3];
    const void*  DS = d_in[4];
    const void*  PS = d_in[5];
    float* out = (float*)d_out;

    const int batch = in_sizes[0] / N_IN;   // 256

    const size_t smem = (N_IN + 16) * sizeof(float);  // row + sentinel + pad
    cudaFuncSetAttribute(feat_kernel,
                         cudaFuncAttributeMaxDynamicSharedMemorySize,
                         (int)smem);

    dim3 grid(NCONV / CPB, batch);
    feat_kernel<<<grid, TPB, smem>>>(x, W, B, KS, DS, PS, out);
}

// round 5
// speedup vs baseline: 1.0030x; 1.0014x over previous
#include <cuda_runtime.h>
#include <math_constants.h>

#define N_IN   16384
#define NCONV  128
#define KMAX   11
#define TPB    256
#define CPB    16   // convs per block

__device__ __forceinline__ float warpReduceMax(float v) {
#pragma unroll
    for (int o = 16; o > 0; o >>= 1)
        v = fmaxf(v, __shfl_xor_sync(0xffffffffu, v, o));
    return v;
}
__device__ __forceinline__ int warpReduceSum(int v) {
#pragma unroll
    for (int o = 16; o > 0; o >>= 1)
        v += __shfl_xor_sync(0xffffffffu, v, o);
    return v;
}

// Read element c of an integer metadata array that may be int64 or int32.
__device__ __forceinline__ int meta_at(const void* arr, int c, bool is64) {
    if (is64) return (int)((const long long*)arr)[c];
    return ((const int*)arr)[c];
}

// Compute per-thread partial (max, neg-count) for one conv.
// xs: smem copy of x row, with xs[N_IN] == 0.0f sentinel for padding.
template <int K>
__device__ __forceinline__ void conv_feat(
    const float* __restrict__ xs,
    const float* __restrict__ wrow, float bias,
    int d, int p, int L,
    float& mx_out, int& neg_out)
{
    float w[K];
#pragma unroll
    for (int j = 0; j < K; j++) w[j] = wrow[j];
    int off[K];
#pragma unroll
    for (int j = 0; j < K; j++) off[j] = j * d;

    float mx = -CUDART_INF_F;
    int   neg = 0;
    const int tid = threadIdx.x;

    // middle zone [m_lo, m_hi): all K taps in-range (t>=p and t-p+(K-1)d <= N-1)
    const int m_lo = min(p, L);
    const int m_hi = max(m_lo, L - p);

    // ---- left edge: clamped taps ----
    for (int t = tid; t < m_lo; t += TPB) {
        float y = bias;
#pragma unroll
        for (int j = 0; j < K; j++) {
            int idx = t - p + off[j];
            unsigned ui = min((unsigned)idx, (unsigned)N_IN); // OOB -> sentinel
            y = fmaf(w[j], xs[ui], y);
        }
        mx = fmaxf(mx, y);
        neg += (int)(__float_as_uint(y) >> 31);
    }

    // ---- middle: no bounds checks (hot loop) ----
    for (int t = m_lo + tid; t < m_hi; t += TPB) {
        const float* xb = xs + (t - p);
        float y = bias;
#pragma unroll
        for (int j = 0; j < K; j++)
            y = fmaf(w[j], xb[off[j]], y);
        mx = fmaxf(mx, y);
        neg += (int)(__float_as_uint(y) >> 31);
    }

    // ---- right edge: clamped taps ----
    for (int t = m_hi + tid; t < L; t += TPB) {
        float y = bias;
#pragma unroll
        for (int j = 0; j < K; j++) {
            int idx = t - p + off[j];
            unsigned ui = min((unsigned)idx, (unsigned)N_IN);
            y = fmaf(w[j], xs[ui], y);
        }
        mx = fmaxf(mx, y);
        neg += (int)(__float_as_uint(y) >> 31);
    }

    mx_out = mx;
    neg_out = neg;
}

__global__ void __launch_bounds__(TPB)
feat_kernel(const float* __restrict__ x,
            const float* __restrict__ W,
            const float* __restrict__ B,
            const void* __restrict__ KS,
            const void* __restrict__ DS,
            const void* __restrict__ PS,
            float* __restrict__ out)
{
    extern __shared__ float xs[];   // N_IN + sentinel
    const int b = blockIdx.y;

    // Load x row into smem (float4 vectorized).
    {
        const float4* xr4 = (const float4*)(x + (size_t)b * N_IN);
        float4* xs4 = (float4*)xs;
        for (int i = threadIdx.x; i < N_IN / 4; i += TPB)
            xs4[i] = xr4[i];
        if (threadIdx.x == 0) xs[N_IN] = 0.0f;
    }

    __shared__ float rmax[TPB / 32];
    __shared__ int   rneg[TPB / 32];
    __syncthreads();

    // Detect int64 vs int32 metadata: kernel_sizes[0] in [7,11], so for int64
    // the second 32-bit word is 0; for int32 it is kernel_sizes[1] (>=7).
    const bool is64 = (((const int*)KS)[1] == 0);

    const int c0 = blockIdx.x * CPB;
    for (int c = c0; c < c0 + CPB; ++c) {
        const int k = meta_at(KS, c, is64);
        const int d = meta_at(DS, c, is64);
        const int p = meta_at(PS, c, is64);
        const int L = N_IN + 2 * p - d * (k - 1);

        const float* wrow = W + c * KMAX;
        const float bias  = B[c];

        float mx; int neg;
        if (k == 7)       conv_feat<7 >(xs, wrow, bias, d, p, L, mx, neg);
        else if (k == 9)  conv_feat<9 >(xs, wrow, bias, d, p, L, mx, neg);
        else              conv_feat<11>(xs, wrow, bias, d, p, L, mx, neg);

        // block reduction
        mx  = warpReduceMax(mx);
        neg = warpReduceSum(neg);
        const int warp = threadIdx.x >> 5;
        const int lane = threadIdx.x & 31;
        if (lane == 0) { rmax[warp] = mx; rneg[warp] = neg; }
        __syncthreads();
        if (threadIdx.x == 0) {
            float m = rmax[0]; int n = rneg[0];
#pragma unroll
            for (int i = 1; i < TPB / 32; i++) {
                m = fmaxf(m, rmax[i]);
                n += rneg[i];
            }
            const size_t base = (size_t)b * (2 * NCONV) + 2 * c;
            out[base]     = m;
            out[base + 1] = (float)(L - n) / (float)L;   // ppv = count(y>=0)/L
        }
        __syncthreads();   // protect rmax/rneg reuse for next conv
    }
}

extern "C" void kernel_launch(void* const* d_in, const int* in_sizes, int n_in,
                              void* d_out, int out_size)
{
    const float* x  = (const float*)d_in[0];
    const float* W  = (const float*)d_in[1];
    const float* B  = (const float*)d_in[2];
    const void*  KS = d_in[3];
    const void*  DS = d_in[4];
    const void*  PS = d_in[5];
    float* out = (float*)d_out;

    const int batch = in_sizes[0] / N_IN;   // 256

    const size_t smem = (N_IN + 16) * sizeof(float);  // row + sentinel + pad
    cudaFuncSetAttribute(feat_kernel,
                         cudaFuncAttributeMaxDynamicSharedMemorySize,
                         (int)smem);

    dim3 grid(NCONV / CPB, batch);
    feat_kernel<<<grid, TPB, smem>>>(x, W, B, KS, DS, PS, out);
}

// round 6
// speedup vs baseline: 1.2293x; 1.2256x over previous
#include <cuda_runtime.h>
#include <math_constants.h>

#define N_IN   16384
#define NCONV  128
#define KMAX   11
#define TPB    256
#define CPB    16    // convs per block
#define CHUNK  65    // 65 == 1 (mod 32) -> conflict-free lanes for any dilation

__device__ __forceinline__ float warpReduceMax(float v) {
#pragma unroll
    for (int o = 16; o > 0; o >>= 1)
        v = fmaxf(v, __shfl_xor_sync(0xffffffffu, v, o));
    return v;
}
__device__ __forceinline__ int warpReduceSum(int v) {
#pragma unroll
    for (int o = 16; o > 0; o >>= 1)
        v += __shfl_xor_sync(0xffffffffu, v, o);
    return v;
}

// Read element c of an integer metadata array that may be int64 or int32.
__device__ __forceinline__ int meta_at(const void* arr, int c, bool is64) {
    if (is64) return (int)((const long long*)arr)[c];
    return ((const int*)arr)[c];
}

// Decimated sliding-window FIR for one conv.
// Outputs u = t - p = r + m*d; taps of output m are z[m..m+K-1], z[m] = xs[r+m*d]
// (clamped to zero-sentinel xs[N_IN] when out of range).
template <int K>
__device__ __forceinline__ void conv_feat_dec(
    const float* __restrict__ xs,
    const float* __restrict__ wrow, float bias,
    int d, int p, int L,
    float& mx_out, int& neg_out)
{
    float w[K];
#pragma unroll
    for (int j = 0; j < K; j++) w[j] = wrow[j];

    float mx = -CUDART_INF_F;
    int   neg = 0;

    // Phase lengths are in {floor(L/d), ceil(L/d)}.
    const int maxlen = (L + d - 1) / d;
    int C, nItems;
    if (d >= TPB) { C = maxlen; nItems = d; }
    else          { C = CHUNK;  nItems = d * ((maxlen + CHUNK - 1) / CHUNK); }

    for (int j = threadIdx.x; j < nItems; j += TPB) {
        const int r = j % d;
        const int q = j / d;

        // m-range of phase r: u in [-p, L-1-p], u = r + m*d
        const int m_lo = -((p + r) / d);
        const int num  = L - 1 - p - r;
        const int m_hi = (num >= 0) ? (num / d) : -((-num + d - 1) / d);

        const int m0 = m_lo + q * C;
        const int m1 = min(m0 + C, m_hi + 1);
        const int len = m1 - m0;
        if (len <= 0) continue;

        // Preload window z[s] = tap (m0+s), s = 0..K-1.
        float z[K];
        int ix = r + m0 * d;
#pragma unroll
        for (int s = 0; s < K; s++) {
            unsigned ui = min((unsigned)ix, (unsigned)N_IN);
            z[s] = xs[ui];
            ix += d;
        }
        // ix = index of tap m0+K (next to load)

        const int full = len / K;
        const int rem  = len - full * K;

        for (int g = 0; g < full; g++) {
#pragma unroll
            for (int s = 0; s < K; s++) {
                float y = fmaf(w[0], z[s % K], bias);
#pragma unroll
                for (int t = 1; t < K; t++)
                    y = fmaf(w[t], z[(s + t) % K], y);
                mx = fmaxf(mx, y);
                neg += (int)(__float_as_uint(y) >> 31);
                // replace oldest (z[m+s]) with z[m+s+K]
                unsigned ui = min((unsigned)ix, (unsigned)N_IN);
                z[s] = xs[ui];
                ix += d;
            }
        }
        if (rem) {
#pragma unroll
            for (int s = 0; s < K; s++) {
                float y = fmaf(w[0], z[s % K], bias);
#pragma unroll
                for (int t = 1; t < K; t++)
                    y = fmaf(w[t], z[(s + t) % K], y);
                if (s < rem) {
                    mx = fmaxf(mx, y);
                    neg += (int)(__float_as_uint(y) >> 31);
                }
                unsigned ui = min((unsigned)ix, (unsigned)N_IN);
                z[s] = xs[ui];
                ix += d;
            }
        }
    }

    mx_out = mx;
    neg_out = neg;
}

__global__ void __launch_bounds__(TPB)
feat_kernel(const float* __restrict__ x,
            const float* __restrict__ W,
            const float* __restrict__ B,
            const void* __restrict__ KS,
            const void* __restrict__ DS,
            const void* __restrict__ PS,
            float* __restrict__ out)
{
    extern __shared__ float xs[];   // N_IN + zero sentinel
    const int b = blockIdx.y;

    {
        const float4* xr4 = (const float4*)(x + (size_t)b * N_IN);
        float4* xs4 = (float4*)xs;
        for (int i = threadIdx.x; i < N_IN / 4; i += TPB)
            xs4[i] = xr4[i];
        if (threadIdx.x == 0) xs[N_IN] = 0.0f;
    }

    __shared__ float rmax[TPB / 32];
    __shared__ int   rneg[TPB / 32];
    __syncthreads();

    // int64 vs int32 metadata: kernel_sizes[0] in {7,9,11}; for int64 the
    // second 32-bit word is 0, for int32 it's kernel_sizes[1] (>=7).
    const bool is64 = (((const int*)KS)[1] == 0);

    const int c0 = blockIdx.x * CPB;
    for (int c = c0; c < c0 + CPB; ++c) {
        const int k = meta_at(KS, c, is64);
        const int d = meta_at(DS, c, is64);
        const int p = meta_at(PS, c, is64);
        const int L = N_IN + 2 * p - d * (k - 1);

        const float* wrow = W + c * KMAX;
        const float bias  = B[c];

        float mx; int neg;
        if (k == 7)       conv_feat_dec<7 >(xs, wrow, bias, d, p, L, mx, neg);
        else if (k == 9)  conv_feat_dec<9 >(xs, wrow, bias, d, p, L, mx, neg);
        else              conv_feat_dec<11>(xs, wrow, bias, d, p, L, mx, neg);

        mx  = warpReduceMax(mx);
        neg = warpReduceSum(neg);
        const int warp = threadIdx.x >> 5;
        const int lane = threadIdx.x & 31;
        if (lane == 0) { rmax[warp] = mx; rneg[warp] = neg; }
        __syncthreads();
        if (threadIdx.x == 0) {
            float m = rmax[0]; int n = rneg[0];
#pragma unroll
            for (int i = 1; i < TPB / 32; i++) {
                m = fmaxf(m, rmax[i]);
                n += rneg[i];
            }
            const size_t base = (size_t)b * (2 * NCONV) + 2 * c;
            out[base]     = m;
            out[base + 1] = (float)(L - n) / (float)L;
        }
        __syncthreads();
    }
}

extern "C" void kernel_launch(void* const* d_in, const int* in_sizes, int n_in,
                              void* d_out, int out_size)
{
    const float* x  = (const float*)d_in[0];
    const float* W  = (const float*)d_in[1];
    const float* B  = (const float*)d_in[2];
    const void*  KS = d_in[3];
    const void*  DS = d_in[4];
    const void*  PS = d_in[5];
    float* out = (float*)d_out;

    const int batch = in_sizes[0] / N_IN;   // 256

    const size_t smem = (N_IN + 16) * sizeof(float);
    cudaFuncSetAttribute(feat_kernel,
                         cudaFuncAttributeMaxDynamicSharedMemorySize,
                         (int)smem);

    dim3 grid(NCONV / CPB, batch);
    feat_kernel<<<grid, TPB, smem>>>(x, W, B, KS, DS, PS, out);
}

// round 7
// speedup vs baseline: 1.2296x; 1.0002x over previous
#include <cuda_runtime.h>
#include <math_constants.h>

#define N_IN   16384
#define NCONV  128
#define KMAX   11
#define TPB    256
#define CPB    16    // convs per block
#define CHUNK  65    // 65 == 1 (mod 32) -> conflict-free lanes for any dilation

__device__ __forceinline__ float warpReduceMax(float v) {
#pragma unroll
    for (int o = 16; o > 0; o >>= 1)
        v = fmaxf(v, __shfl_xor_sync(0xffffffffu, v, o));
    return v;
}
__device__ __forceinline__ int warpReduceSum(int v) {
#pragma unroll
    for (int o = 16; o > 0; o >>= 1)
        v += __shfl_xor_sync(0xffffffffu, v, o);
    return v;
}

// Read element c of an integer metadata array that may be int64 or int32.
__device__ __forceinline__ int meta_at(const void* arr, int c, bool is64) {
    if (is64) return (int)((const long long*)arr)[c];
    return ((const int*)arr)[c];
}

// Decimated sliding-window FIR for one conv.
// Outputs u = t - p = r + m*d; taps of output m are z[m..m+K-1], z[m] = xs[r+m*d]
// (clamped to zero-sentinel xs[N_IN] when out of range).
template <int K>
__device__ __forceinline__ void conv_feat_dec(
    const float* __restrict__ xs,
    const float* __restrict__ wrow, float bias,
    int d, int p, int L,
    float& mx_out, int& neg_out)
{
    float w[K];
#pragma unroll
    for (int j = 0; j < K; j++) w[j] = wrow[j];

    float mx = -CUDART_INF_F;
    int   neg = 0;

    // Phase lengths are in {floor(L/d), ceil(L/d)}.
    const int maxlen = (L + d - 1) / d;
    int C, nItems;
    if (d >= TPB) { C = maxlen; nItems = d; }
    else          { C = CHUNK;  nItems = d * ((maxlen + CHUNK - 1) / CHUNK); }

    for (int j = threadIdx.x; j < nItems; j += TPB) {
        const int r = j % d;
        const int q = j / d;

        // m-range of phase r: u in [-p, L-1-p], u = r + m*d
        const int m_lo = -((p + r) / d);
        const int num  = L - 1 - p - r;
        const int m_hi = (num >= 0) ? (num / d) : -((-num + d - 1) / d);

        const int m0 = m_lo + q * C;
        const int m1 = min(m0 + C, m_hi + 1);
        const int len = m1 - m0;
        if (len <= 0) continue;

        // Preload window z[s] = tap (m0+s), s = 0..K-1.
        float z[K];
        int ix = r + m0 * d;
#pragma unroll
        for (int s = 0; s < K; s++) {
            unsigned ui = min((unsigned)ix, (unsigned)N_IN);
            z[s] = xs[ui];
            ix += d;
        }
        // ix = index of tap m0+K (next to load)

        const int full = len / K;
        const int rem  = len - full * K;

        for (int g = 0; g < full; g++) {
#pragma unroll
            for (int s = 0; s < K; s++) {
                float y = fmaf(w[0], z[s % K], bias);
#pragma unroll
                for (int t = 1; t < K; t++)
                    y = fmaf(w[t], z[(s + t) % K], y);
                mx = fmaxf(mx, y);
                neg += (int)(__float_as_uint(y) >> 31);
                // replace oldest (z[m+s]) with z[m+s+K]
                unsigned ui = min((unsigned)ix, (unsigned)N_IN);
                z[s] = xs[ui];
                ix += d;
            }
        }
        if (rem) {
#pragma unroll
            for (int s = 0; s < K; s++) {
                float y = fmaf(w[0], z[s % K], bias);
#pragma unroll
                for (int t = 1; t < K; t++)
                    y = fmaf(w[t], z[(s + t) % K], y);
                if (s < rem) {
                    mx = fmaxf(mx, y);
                    neg += (int)(__float_as_uint(y) >> 31);
                }
                unsigned ui = min((unsigned)ix, (unsigned)N_IN);
                z[s] = xs[ui];
                ix += d;
            }
        }
    }

    mx_out = mx;
    neg_out = neg;
}

__global__ void __launch_bounds__(TPB)
feat_kernel(const float* __restrict__ x,
            const float* __restrict__ W,
            const float* __restrict__ B,
            const void* __restrict__ KS,
            const void* __restrict__ DS,
            const void* __restrict__ PS,
            float* __restrict__ out)
{
    extern __shared__ float xs[];   // N_IN + zero sentinel
    const int b = blockIdx.y;

    {
        const float4* xr4 = (const float4*)(x + (size_t)b * N_IN);
        float4* xs4 = (float4*)xs;
        for (int i = threadIdx.x; i < N_IN / 4; i += TPB)
            xs4[i] = xr4[i];
        if (threadIdx.x == 0) xs[N_IN] = 0.0f;
    }

    __shared__ float rmax[TPB / 32];
    __shared__ int   rneg[TPB / 32];
    __syncthreads();

    // int64 vs int32 metadata: kernel_sizes[0] in {7,9,11}; for int64 the
    // second 32-bit word is 0, for int32 it's kernel_sizes[1] (>=7).
    const bool is64 = (((const int*)KS)[1] == 0);

    const int c0 = blockIdx.x * CPB;
    for (int c = c0; c < c0 + CPB; ++c) {
        const int k = meta_at(KS, c, is64);
        const int d = meta_at(DS, c, is64);
        const int p = meta_at(PS, c, is64);
        const int L = N_IN + 2 * p - d * (k - 1);

        const float* wrow = W + c * KMAX;
        const float bias  = B[c];

        float mx; int neg;
        if (k == 7)       conv_feat_dec<7 >(xs, wrow, bias, d, p, L, mx, neg);
        else if (k == 9)  conv_feat_dec<9 >(xs, wrow, bias, d, p, L, mx, neg);
        else              conv_feat_dec<11>(xs, wrow, bias, d, p, L, mx, neg);

        mx  = warpReduceMax(mx);
        neg = warpReduceSum(neg);
        const int warp = threadIdx.x >> 5;
        const int lane = threadIdx.x & 31;
        if (lane == 0) { rmax[warp] = mx; rneg[warp] = neg; }
        __syncthreads();
        if (threadIdx.x == 0) {
            float m = rmax[0]; int n = rneg[0];
#pragma unroll
            for (int i = 1; i < TPB / 32; i++) {
                m = fmaxf(m, rmax[i]);
                n += rneg[i];
            }
            const size_t base = (size_t)b * (2 * NCONV) + 2 * c;
            out[base]     = m;
            out[base + 1] = (float)(L - n) / (float)L;
        }
        __syncthreads();
    }
}

extern "C" void kernel_launch(void* const* d_in, const int* in_sizes, int n_in,
                              void* d_out, int out_size)
{
    const float* x  = (const float*)d_in[0];
    const float* W  = (const float*)d_in[1];
    const float* B  = (const float*)d_in[2];
    const void*  KS = d_in[3];
    const void*  DS = d_in[4];
    const void*  PS = d_in[5];
    float* out = (float*)d_out;

    const int batch = in_sizes[0] / N_IN;   // 256

    const size_t smem = (N_IN + 16) * sizeof(float);
    cudaFuncSetAttribute(feat_kernel,
                         cudaFuncAttributeMaxDynamicSharedMemorySize,
                         (int)smem);

    dim3 grid(NCONV / CPB, batch);
    feat_kernel<<<grid, TPB, smem>>>(x, W, B, KS, DS, PS, out);
}

// round 9
// speedup vs baseline: 1.4334x; 1.1657x over previous
#include <cuda_runtime.h>
#include <math_constants.h>

#define N_IN   16384
#define NCONV  128
#define KMAX   11
#define TPB    256
#define CPB    16    // convs per block
#define CHUNK  65    // 65 == 1 (mod 32) -> conflict-free lanes for any dilation

__device__ __forceinline__ float warpReduceMax(float v) {
#pragma unroll
    for (int o = 16; o > 0; o >>= 1)
        v = fmaxf(v, __shfl_xor_sync(0xffffffffu, v, o));
    return v;
}
__device__ __forceinline__ int warpReduceSum(int v) {
#pragma unroll
    for (int o = 16; o > 0; o >>= 1)
        v += __shfl_xor_sync(0xffffffffu, v, o);
    return v;
}

__device__ __forceinline__ int meta_at(const void* arr, int c, bool is64) {
    if (is64) return (int)((const long long*)arr)[c];
    return ((const int*)arr)[c];
}

// ---- ring FIR, no bounds checks. Loads exactly len+K-1 taps:
// preload K-1, then load-one/compute-one. Max address: i0+(len+K-2)*d. ----
template <int K>
__device__ __forceinline__ void ring_fast(
    const float* __restrict__ xs, const float* __restrict__ w, float bias,
    int i0, int d, int len, float& mx, int& neg)
{
    const float* ptr = xs + i0;
    float z[K];
#pragma unroll
    for (int s = 0; s < K - 1; s++) { z[s] = *ptr; ptr += d; }

    const int full = len / K;
    const int rem  = len - full * K;

    for (int g = 0; g < full; g++) {
#pragma unroll
        for (int s = 0; s < K; s++) {
            z[(s + K - 1) % K] = *ptr; ptr += d;   // newest tap
            float y = fmaf(w[0], z[s % K], bias);
#pragma unroll
            for (int t = 1; t < K; t++)
                y = fmaf(w[t], z[(s + t) % K], y);
            mx = fmaxf(mx, y);
            neg += (int)(__float_as_uint(y) >> 31);
        }
    }
    if (rem) {
#pragma unroll
        for (int s = 0; s < K; s++) {
            if (s < rem) {
                z[(s + K - 1) % K] = *ptr; ptr += d;
                float y = fmaf(w[0], z[s % K], bias);
#pragma unroll
                for (int t = 1; t < K; t++)
                    y = fmaf(w[t], z[(s + t) % K], y);
                mx = fmaxf(mx, y);
                neg += (int)(__float_as_uint(y) >> 31);
            }
        }
    }
}

// ---- same ring, OOB taps clamped to zero sentinel xs[N_IN] (edge chunks) ----
template <int K>
__device__ __forceinline__ void ring_clamped(
    const float* __restrict__ xs, const float* __restrict__ w, float bias,
    int i0, int d, int len, float& mx, int& neg)
{
    int ix = i0;
    float z[K];
#pragma unroll
    for (int s = 0; s < K - 1; s++) {
        unsigned ui = min((unsigned)ix, (unsigned)N_IN);
        z[s] = xs[ui]; ix += d;
    }

    const int full = len / K;
    const int rem  = len - full * K;

    for (int g = 0; g < full; g++) {
#pragma unroll
        for (int s = 0; s < K; s++) {
            unsigned ui = min((unsigned)ix, (unsigned)N_IN);
            z[(s + K - 1) % K] = xs[ui]; ix += d;
            float y = fmaf(w[0], z[s % K], bias);
#pragma unroll
            for (int t = 1; t < K; t++)
                y = fmaf(w[t], z[(s + t) % K], y);
            mx = fmaxf(mx, y);
            neg += (int)(__float_as_uint(y) >> 31);
        }
    }
    if (rem) {
#pragma unroll
        for (int s = 0; s < K; s++) {
            if (s < rem) {
                unsigned ui = min((unsigned)ix, (unsigned)N_IN);
                z[(s + K - 1) % K] = xs[ui]; ix += d;
                float y = fmaf(w[0], z[s % K], bias);
#pragma unroll
                for (int t = 1; t < K; t++)
                    y = fmaf(w[t], z[(s + t) % K], y);
                mx = fmaxf(mx, y);
                neg += (int)(__float_as_uint(y) >> 31);
            }
        }
    }
}

template <int K>
__device__ __forceinline__ void conv_feat_dec(
    const float* __restrict__ xs,
    const float* __restrict__ wrow, float bias,
    int d, int p, int L,
    float& mx_out, int& neg_out)
{
    float w[K];
#pragma unroll
    for (int j = 0; j < K; j++) w[j] = wrow[j];

    float mx = -CUDART_INF_F;
    int   neg = 0;

    // Per-conv division results (2 divides total, amortized over all items):
    //   floor((p+r)/d) = pq + (prm + r >= d)   for r in [0,d)
    //   floor((A-r)/d) = aq  - (r > arm)       for r in [0,d), A >= 0
    const int A   = L - 1 - p;
    const int pq  = p / d, prm = p - pq * d;
    const int aq  = A / d, arm = A - aq * d;

    if (d >= TPB) {
        // one item per phase; full phase in one chunk
        for (int r = threadIdx.x; r < d; r += TPB) {
            const int m_lo = -(pq + ((prm + r) >= d ? 1 : 0));
            const int m_hi = aq - (r > arm ? 1 : 0);
            const int len  = m_hi - m_lo + 1;
            if (len <= 0) continue;
            const int i0 = r + m_lo * d;
            if (i0 >= 0 && i0 + (len + K - 2) * d < N_IN)
                ring_fast<K>(xs, w, bias, i0, d, len, mx, neg);
            else
                ring_clamped<K>(xs, w, bias, i0, d, len, mx, neg);
        }
    } else {
        const int maxlen = (L + d - 1) / d;
        const int nQ     = (maxlen + CHUNK - 1) / CHUNK;
        const int nItems = d * nQ;
        const float rd   = 1.0f / (float)d;

        for (int j = threadIdx.x; j < nItems; j += TPB) {
            // q = j / d, r = j % d via float reciprocal (+/-1 fixup); j < ~512
            int q = (int)((float)j * rd);
            int r = j - q * d;
            if (r < 0)       { r += d; q--; }
            else if (r >= d) { r -= d; q++; }

            const int m_lo = -(pq + ((prm + r) >= d ? 1 : 0));
            const int m_hi = aq - (r > arm ? 1 : 0);
            const int m0   = m_lo + q * CHUNK;
            const int m1   = min(m0 + CHUNK, m_hi + 1);
            const int len  = m1 - m0;
            if (len <= 0) continue;
            const int i0 = r + m0 * d;
            if (i0 >= 0 && i0 + (len + K - 2) * d < N_IN)
                ring_fast<K>(xs, w, bias, i0, d, len, mx, neg);
            else
                ring_clamped<K>(xs, w, bias, i0, d, len, mx, neg);
        }
    }

    mx_out = mx;
    neg_out = neg;
}

__global__ void __launch_bounds__(TPB)
feat_kernel(const float* __restrict__ x,
            const float* __restrict__ W,
            const float* __restrict__ B,
            const void* __restrict__ KS,
            const void* __restrict__ DS,
            const void* __restrict__ PS,
            float* __restrict__ out)
{
    extern __shared__ float xs[];   // N_IN + zero sentinel
    const int b = blockIdx.y;

    {
        const float4* xr4 = (const float4*)(x + (size_t)b * N_IN);
        float4* xs4 = (float4*)xs;
        for (int i = threadIdx.x; i < N_IN / 4; i += TPB)
            xs4[i] = xr4[i];
        if (threadIdx.x == 0) xs[N_IN] = 0.0f;
    }

    __shared__ float rmax[TPB / 32];
    __shared__ int   rneg[TPB / 32];
    __syncthreads();

    // int64 vs int32 metadata: kernel_sizes[0] in {7,9,11}; for int64 the
    // second 32-bit word is 0, for int32 it's kernel_sizes[1] (>=7).
    const bool is64 = (((const int*)KS)[1] == 0);

    const int c0 = blockIdx.x * CPB;
    for (int c = c0; c < c0 + CPB; ++c) {
        const int k = meta_at(KS, c, is64);
        const int d = meta_at(DS, c, is64);
        const int p = meta_at(PS, c, is64);
        const int L = N_IN + 2 * p - d * (k - 1);

        const float* wrow = W + c * KMAX;
        const float bias  = B[c];

        float mx; int neg;
        if (k == 7)       conv_feat_dec<7 >(xs, wrow, bias, d, p, L, mx, neg);
        else if (k == 9)  conv_feat_dec<9 >(xs, wrow, bias, d, p, L, mx, neg);
        else              conv_feat_dec<11>(xs, wrow, bias, d, p, L, mx, neg);

        mx  = warpReduceMax(mx);
        neg = warpReduceSum(neg);
        const int warp = threadIdx.x >> 5;
        const int lane = threadIdx.x & 31;
        if (lane == 0) { rmax[warp] = mx; rneg[warp] = neg; }
        __syncthreads();
        if (threadIdx.x == 0) {
            float m = rmax[0]; int n = rneg[0];
#pragma unroll
            for (int i = 1; i < TPB / 32; i++) {
                m = fmaxf(m, rmax[i]);
                n += rneg[i];
            }
            const size_t base = (size_t)b * (2 * NCONV) + 2 * c;
            out[base]     = m;
            out[base + 1] = (float)(L - n) / (float)L;
        }
        __syncthreads();
    }
}

extern "C" void kernel_launch(void* const* d_in, const int* in_sizes, int n_in,
                              void* d_out, int out_size)
{
    const float* x  = (const float*)d_in[0];
    const float* W  = (const float*)d_in[1];
    const float* B  = (const float*)d_in[2];
    const void*  KS = d_in[3];
    const void*  DS = d_in[4];
    const void*  PS = d_in[5];
    float* out = (float*)d_out;

    const int batch = in_sizes[0] / N_IN;   // 256

    const size_t smem = (N_IN + 16) * sizeof(float);
    cudaFuncSetAttribute(feat_kernel,
                         cudaFuncAttributeMaxDynamicSharedMemorySize,
                         (int)smem);

    dim3 grid(NCONV / CPB, batch);
    feat_kernel<<<grid, TPB, smem>>>(x, W, B, KS, DS, PS, out);
}